// round 3
// baseline (speedup 1.0000x reference)
#include <cuda_runtime.h>

#define NNODES 507904
#define NEDGES 4063232
#define HID 64
#define NGRAPHS 8192
#define NPG 62
#define BN_EPS 1e-5f
#define FN ((float)NNODES)
#define APAD 68

// -------- device scratch (no allocations allowed) --------
__device__ float g_h[(size_t)NNODES * HID];     // pre-BN post-relu activations r (gather source)
__device__ float g_agg[(size_t)NNODES * HID];   // r_i + sum_{j->i} r_j  (next-layer input, pre-fold)
__device__ float g_agg1[(size_t)NNODES * 4];    // layer-1: x_i + sum x_j
__device__ float g_stat[6 * HID];               // [sum0,sq0, sum1,sq1, sum2,sq2]
__device__ int   g_deg[NNODES];

__device__ __forceinline__ void red4(float* p, float4 v) {
    asm volatile("red.global.add.v4.f32 [%0], {%1,%2,%3,%4};"
                 :: "l"(p), "f"(v.x), "f"(v.y), "f"(v.z), "f"(v.w)
                 : "memory");
}

// -------- setup kernels --------
__global__ void k_zero() {
    int i = blockIdx.x * blockDim.x + threadIdx.x;
    if (i < NNODES) g_deg[i] = 0;
    if (i < 6 * HID) g_stat[i] = 0.f;
}

__global__ void k_deg(const int* __restrict__ dst) {
    int e = blockIdx.x * blockDim.x + threadIdx.x;
    if (e < NEDGES) atomicAdd(&g_deg[dst[e]], 1);
}

__global__ void k_initagg1(const float* __restrict__ x) {
    int i = blockIdx.x * blockDim.x + threadIdx.x;
    if (i < NNODES) ((float4*)g_agg1)[i] = ((const float4*)x)[i];
}

// -------- edge scatter kernels --------
__global__ void k_edge1(const float* __restrict__ x,
                        const int* __restrict__ src, const int* __restrict__ dst) {
    int e = blockIdx.x * blockDim.x + threadIdx.x;
    if (e < NEDGES) {
        int s = src[e], d = dst[e];
        float4 v = ((const float4*)x)[s];
        red4(&g_agg1[(size_t)d * 4], v);
    }
}

// one thread per (edge, float4-chunk): 16 chunks per edge (64 ch)
__global__ void k_edge64(const int* __restrict__ src, const int* __restrict__ dst) {
    int gid = blockIdx.x * blockDim.x + threadIdx.x;
    int e = gid >> 4;
    int q = gid & 15;
    if (e < NEDGES) {
        int s = src[e], d = dst[e];
        float4 v = ((const float4*)(g_h + (size_t)s * HID))[q];
        red4(g_agg + (size_t)d * HID + (size_t)q * 4, v);
    }
}

// -------- fused GIN MLP: input-fold(BN) -> GEMM1 -> relu -> GEMM2 -> relu -> stats --------
// Block: 256 threads, 64 nodes. Thread tile: 4 nodes x 4 channels.
template<int KIN, bool BNFOLD, bool WRITE_AGG>
__global__ __launch_bounds__(256) void k_mlp(
    const float* __restrict__ Wa, const float* __restrict__ ba,
    const float* __restrict__ Wb, const float* __restrict__ bb,
    const float* __restrict__ gamma, const float* __restrict__ beta,
    int stat_in_off, int stat_out_off)
{
    __shared__ float sA[64 * APAD];
    __shared__ float sW[64 * 64];
    __shared__ float sBias[64];
    __shared__ float sS[64], sT[64], sFd[64];
    __shared__ float sStat[128];

    const int tid = threadIdx.x;
    const int nb = blockIdx.x * 64;

    if (tid < 128) sStat[tid] = 0.f;
    if (BNFOLD) {
        if (tid < 64) {
            float sum = g_stat[stat_in_off + tid];
            float sq  = g_stat[stat_in_off + 64 + tid];
            float mean = sum / FN;
            float var  = sq / FN - mean * mean;
            float inv  = rsqrtf(var + BN_EPS);
            float s    = gamma[tid] * inv;
            sS[tid] = s;
            sT[tid] = beta[tid] - mean * s;
            sFd[tid] = 1.f + (float)g_deg[nb + tid];
        }
    }
    if (tid < 64) sBias[tid] = ba[tid];
    for (int i = tid; i < KIN * 64; i += 256) sW[i] = Wa[i];
    __syncthreads();

    // load input tile (with BN fold)
    if (KIN == 4) {
        int m = tid >> 2, k = tid & 3;
        sA[m * APAD + k] = g_agg1[(size_t)(nb + m) * 4 + k];
    } else {
        for (int i = tid; i < 64 * 64; i += 256) {
            int m = i >> 6, k = i & 63;
            float v = g_agg[(size_t)(nb + m) * 64 + k];
            sA[m * APAD + k] = BNFOLD ? (sS[k] * v + sFd[m] * sT[k]) : v;
        }
    }
    __syncthreads();

    const int mt = tid >> 4;   // 0..15
    const int nt = tid & 15;   // 0..15

    float acc[4][4];
    #pragma unroll
    for (int i = 0; i < 4; i++)
        #pragma unroll
        for (int j = 0; j < 4; j++) acc[i][j] = 0.f;

    // GEMM1: [64 x KIN] @ [KIN x 64]
    #pragma unroll 4
    for (int k = 0; k < KIN; k++) {
        float a0 = sA[(mt * 4 + 0) * APAD + k];
        float a1 = sA[(mt * 4 + 1) * APAD + k];
        float a2 = sA[(mt * 4 + 2) * APAD + k];
        float a3 = sA[(mt * 4 + 3) * APAD + k];
        float4 b = *(const float4*)&sW[k * 64 + nt * 4];
        acc[0][0] += a0 * b.x; acc[0][1] += a0 * b.y; acc[0][2] += a0 * b.z; acc[0][3] += a0 * b.w;
        acc[1][0] += a1 * b.x; acc[1][1] += a1 * b.y; acc[1][2] += a1 * b.z; acc[1][3] += a1 * b.w;
        acc[2][0] += a2 * b.x; acc[2][1] += a2 * b.y; acc[2][2] += a2 * b.z; acc[2][3] += a2 * b.w;
        acc[3][0] += a3 * b.x; acc[3][1] += a3 * b.y; acc[3][2] += a3 * b.z; acc[3][3] += a3 * b.w;
    }

    // bias into regs before anyone overwrites sBias
    float bj0 = sBias[nt * 4 + 0];
    float bj1 = sBias[nt * 4 + 1];
    float bj2 = sBias[nt * 4 + 2];
    float bj3 = sBias[nt * 4 + 3];
    __syncthreads();   // done reading sA / sBias

    // mid = relu(acc + b1) -> back into sA; reload W2/b2
    #pragma unroll
    for (int i = 0; i < 4; i++) {
        float4 v;
        v.x = fmaxf(acc[i][0] + bj0, 0.f);
        v.y = fmaxf(acc[i][1] + bj1, 0.f);
        v.z = fmaxf(acc[i][2] + bj2, 0.f);
        v.w = fmaxf(acc[i][3] + bj3, 0.f);
        *(float4*)&sA[(mt * 4 + i) * APAD + nt * 4] = v;
    }
    for (int i = tid; i < 64 * 64; i += 256) sW[i] = Wb[i];
    if (tid < 64) sBias[tid] = bb[tid];
    __syncthreads();

    #pragma unroll
    for (int i = 0; i < 4; i++)
        #pragma unroll
        for (int j = 0; j < 4; j++) acc[i][j] = 0.f;

    // GEMM2: [64 x 64] @ [64 x 64]
    #pragma unroll 4
    for (int k = 0; k < 64; k++) {
        float a0 = sA[(mt * 4 + 0) * APAD + k];
        float a1 = sA[(mt * 4 + 1) * APAD + k];
        float a2 = sA[(mt * 4 + 2) * APAD + k];
        float a3 = sA[(mt * 4 + 3) * APAD + k];
        float4 b = *(const float4*)&sW[k * 64 + nt * 4];
        acc[0][0] += a0 * b.x; acc[0][1] += a0 * b.y; acc[0][2] += a0 * b.z; acc[0][3] += a0 * b.w;
        acc[1][0] += a1 * b.x; acc[1][1] += a1 * b.y; acc[1][2] += a1 * b.z; acc[1][3] += a1 * b.w;
        acc[2][0] += a2 * b.x; acc[2][1] += a2 * b.y; acc[2][2] += a2 * b.z; acc[2][3] += a2 * b.w;
        acc[3][0] += a3 * b.x; acc[3][1] += a3 * b.y; acc[3][2] += a3 * b.z; acc[3][3] += a3 * b.w;
    }

    float cj0 = sBias[nt * 4 + 0];
    float cj1 = sBias[nt * 4 + 1];
    float cj2 = sBias[nt * 4 + 2];
    float cj3 = sBias[nt * 4 + 3];

    float psum[4] = {0.f, 0.f, 0.f, 0.f};
    float psq[4]  = {0.f, 0.f, 0.f, 0.f};

    #pragma unroll
    for (int i = 0; i < 4; i++) {
        float4 v;
        v.x = fmaxf(acc[i][0] + cj0, 0.f);
        v.y = fmaxf(acc[i][1] + cj1, 0.f);
        v.z = fmaxf(acc[i][2] + cj2, 0.f);
        v.w = fmaxf(acc[i][3] + cj3, 0.f);
        size_t row = (size_t)(nb + mt * 4 + i) * 64 + (size_t)nt * 4;
        *(float4*)&g_h[row] = v;
        if (WRITE_AGG) *(float4*)&g_agg[row] = v;
        psum[0] += v.x; psq[0] += v.x * v.x;
        psum[1] += v.y; psq[1] += v.y * v.y;
        psum[2] += v.z; psq[2] += v.z * v.z;
        psum[3] += v.w; psq[3] += v.w * v.w;
    }

    // reduce lane l <-> l^16 (same nt, adjacent mt), then shared atomics
    #pragma unroll
    for (int j = 0; j < 4; j++) {
        psum[j] += __shfl_xor_sync(0xffffffffu, psum[j], 16);
        psq[j]  += __shfl_xor_sync(0xffffffffu, psq[j], 16);
    }
    if ((tid & 16) == 0) {
        #pragma unroll
        for (int j = 0; j < 4; j++) {
            atomicAdd(&sStat[nt * 4 + j], psum[j]);
            atomicAdd(&sStat[64 + nt * 4 + j], psq[j]);
        }
    }
    __syncthreads();
    if (tid < 128) atomicAdd(&g_stat[stat_out_off + tid], sStat[tid]);
}

// -------- final: BN3 + per-graph sum-pool + fc --------
__global__ __launch_bounds__(64) void k_final(
    const float* __restrict__ g3, const float* __restrict__ be3,
    const float* __restrict__ Wfc, const float* __restrict__ bfc,
    float* __restrict__ out)
{
    int g = blockIdx.x;
    int c = threadIdx.x;  // 0..63

    float sum = g_stat[4 * 64 + c];
    float sq  = g_stat[5 * 64 + c];
    float mean = sum / FN;
    float var  = sq / FN - mean * mean;
    float inv  = rsqrtf(var + BN_EPS);
    float s    = g3[c] * inv;
    float t    = be3[c] - mean * s;

    const float* base = g_h + (size_t)g * NPG * 64;
    float acc = 0.f;
    #pragma unroll 2
    for (int i = 0; i < NPG; i++) acc += base[(size_t)i * 64 + c];
    float pool = s * acc + (float)NPG * t;

    __shared__ float red[3][64];
    red[0][c] = pool * Wfc[c * 3 + 0];
    red[1][c] = pool * Wfc[c * 3 + 1];
    red[2][c] = pool * Wfc[c * 3 + 2];
    __syncthreads();
    if (c < 3) {
        float a = 0.f;
        #pragma unroll
        for (int i = 0; i < 64; i++) a += red[c][i];
        out[(size_t)g * 3 + c] = a + bfc[c];
    }
}

// -------- launch --------
extern "C" void kernel_launch(void* const* d_in, const int* in_sizes, int n_in,
                              void* d_out, int out_size) {
    (void)in_sizes; (void)n_in; (void)out_size;
    const float* x   = (const float*)d_in[0];
    const int*   src = (const int*)d_in[1];
    const int*   dst = (const int*)d_in[2];
    // d_in[3] = num_graphs (compile-time constant here)
    const float* W1a = (const float*)d_in[4];
    const float* b1a = (const float*)d_in[5];
    const float* W1b = (const float*)d_in[6];
    const float* b1b = (const float*)d_in[7];
    const float* g1  = (const float*)d_in[8];
    const float* be1 = (const float*)d_in[9];
    const float* W2a = (const float*)d_in[10];
    const float* b2a = (const float*)d_in[11];
    const float* W2b = (const float*)d_in[12];
    const float* b2b = (const float*)d_in[13];
    const float* g2  = (const float*)d_in[14];
    const float* be2 = (const float*)d_in[15];
    const float* W3a = (const float*)d_in[16];
    const float* b3a = (const float*)d_in[17];
    const float* W3b = (const float*)d_in[18];
    const float* b3b = (const float*)d_in[19];
    const float* g3  = (const float*)d_in[20];
    const float* be3 = (const float*)d_in[21];
    const float* Wfc = (const float*)d_in[22];
    const float* bfc = (const float*)d_in[23];
    float* out = (float*)d_out;

    const int TPB = 256;
    k_zero<<<(NNODES + TPB - 1) / TPB, TPB>>>();
    k_deg<<<(NEDGES + TPB - 1) / TPB, TPB>>>(dst);
    k_initagg1<<<(NNODES + TPB - 1) / TPB, TPB>>>(x);
    k_edge1<<<(NEDGES + TPB - 1) / TPB, TPB>>>(x, src, dst);

    // layer 1: input 4ch, no BN fold; write agg for layer 2
    k_mlp<4, false, true><<<NNODES / 64, TPB>>>(W1a, b1a, W1b, b1b, nullptr, nullptr, 0, 0);

    k_edge64<<<(NEDGES * 16 + TPB - 1) / TPB, TPB>>>(src, dst);
    // layer 2: fold BN1 into input
    k_mlp<64, true, true><<<NNODES / 64, TPB>>>(W2a, b2a, W2b, b2b, g1, be1, 0, 128);

    k_edge64<<<(NEDGES * 16 + TPB - 1) / TPB, TPB>>>(src, dst);
    // layer 3: fold BN2 into input; no agg write
    k_mlp<64, true, false><<<NNODES / 64, TPB>>>(W3a, b3a, W3b, b3b, g2, be2, 128, 256);

    // BN3 + pool + classifier
    k_final<<<NGRAPHS, 64>>>(g3, be3, Wfc, bfc, out);
}

// round 4
// speedup vs baseline: 1.0021x; 1.0021x over previous
#include <cuda_runtime.h>

#define NNODES 507904
#define NEDGES 4063232
#define HID 64
#define NGRAPHS 8192
#define NPG 62
#define BN_EPS 1e-5f
#define FN ((float)NNODES)
#define APAD 68

// -------- device scratch (no allocations allowed) --------
__device__ float g_h[(size_t)NNODES * HID];     // pre-BN post-relu activations r (gather source)
__device__ float g_agg[(size_t)NNODES * HID];   // r_i + sum_{j->i} r_j  (next-layer input, pre-fold)
__device__ float g_agg1[(size_t)NNODES * 4];    // layer-1: x_i + sum x_j
__device__ float g_stat[6 * HID];               // [sum0,sq0, sum1,sq1, sum2,sq2]
__device__ int   g_deg[NNODES];

__device__ __forceinline__ void red4(float* p, float4 v) {
    asm volatile("red.global.add.v4.f32 [%0], {%1,%2,%3,%4};"
                 :: "l"(p), "f"(v.x), "f"(v.y), "f"(v.z), "f"(v.w)
                 : "memory");
}

// -------- setup kernels --------
__global__ void k_zero() {
    int i = blockIdx.x * blockDim.x + threadIdx.x;
    if (i < NNODES) g_deg[i] = 0;
    if (i < 6 * HID) g_stat[i] = 0.f;
}

__global__ void k_deg(const int* __restrict__ dst) {
    int e = blockIdx.x * blockDim.x + threadIdx.x;
    if (e < NEDGES) atomicAdd(&g_deg[dst[e]], 1);
}

__global__ void k_initagg1(const float* __restrict__ x) {
    int i = blockIdx.x * blockDim.x + threadIdx.x;
    if (i < NNODES) ((float4*)g_agg1)[i] = ((const float4*)x)[i];
}

// -------- edge scatter kernels --------
__global__ void k_edge1(const float* __restrict__ x,
                        const int* __restrict__ src, const int* __restrict__ dst) {
    int e = blockIdx.x * blockDim.x + threadIdx.x;
    if (e < NEDGES) {
        int s = src[e], d = dst[e];
        float4 v = ((const float4*)x)[s];
        red4(&g_agg1[(size_t)d * 4], v);
    }
}

// one thread per (edge, float4-chunk): 16 chunks per edge (64 ch)
__global__ void k_edge64(const int* __restrict__ src, const int* __restrict__ dst) {
    int gid = blockIdx.x * blockDim.x + threadIdx.x;
    int e = gid >> 4;
    int q = gid & 15;
    if (e < NEDGES) {
        int s = src[e], d = dst[e];
        float4 v = ((const float4*)(g_h + (size_t)s * HID))[q];
        red4(g_agg + (size_t)d * HID + (size_t)q * 4, v);
    }
}

// -------- fused GIN MLP: input-fold(BN) -> GEMM1 -> relu -> GEMM2 -> relu -> stats --------
// Block: 256 threads, 64 nodes. Thread tile: 4 nodes x 4 channels.
template<int KIN, bool BNFOLD, bool WRITE_AGG>
__global__ __launch_bounds__(256) void k_mlp(
    const float* __restrict__ Wa, const float* __restrict__ ba,
    const float* __restrict__ Wb, const float* __restrict__ bb,
    const float* __restrict__ gamma, const float* __restrict__ beta,
    int stat_in_off, int stat_out_off)
{
    __shared__ float sA[64 * APAD];
    __shared__ float sW[64 * 64];
    __shared__ float sBias[64];
    __shared__ float sS[64], sT[64], sFd[64];
    __shared__ float sStat[128];

    const int tid = threadIdx.x;
    const int nb = blockIdx.x * 64;

    if (tid < 128) sStat[tid] = 0.f;
    if (BNFOLD) {
        if (tid < 64) {
            float sum = g_stat[stat_in_off + tid];
            float sq  = g_stat[stat_in_off + 64 + tid];
            float mean = sum / FN;
            float var  = sq / FN - mean * mean;
            float inv  = rsqrtf(var + BN_EPS);
            float s    = gamma[tid] * inv;
            sS[tid] = s;
            sT[tid] = beta[tid] - mean * s;
            sFd[tid] = 1.f + (float)g_deg[nb + tid];
        }
    }
    if (tid < 64) sBias[tid] = ba[tid];
    for (int i = tid; i < KIN * 64; i += 256) sW[i] = Wa[i];
    __syncthreads();

    // load input tile (with BN fold)
    if (KIN == 4) {
        int m = tid >> 2, k = tid & 3;
        sA[m * APAD + k] = g_agg1[(size_t)(nb + m) * 4 + k];
    } else {
        for (int i = tid; i < 64 * 64; i += 256) {
            int m = i >> 6, k = i & 63;
            float v = g_agg[(size_t)(nb + m) * 64 + k];
            sA[m * APAD + k] = BNFOLD ? (sS[k] * v + sFd[m] * sT[k]) : v;
        }
    }
    __syncthreads();

    const int mt = tid >> 4;   // 0..15
    const int nt = tid & 15;   // 0..15

    float acc[4][4];
    #pragma unroll
    for (int i = 0; i < 4; i++)
        #pragma unroll
        for (int j = 0; j < 4; j++) acc[i][j] = 0.f;

    // GEMM1: [64 x KIN] @ [KIN x 64]
    #pragma unroll 4
    for (int k = 0; k < KIN; k++) {
        float a0 = sA[(mt * 4 + 0) * APAD + k];
        float a1 = sA[(mt * 4 + 1) * APAD + k];
        float a2 = sA[(mt * 4 + 2) * APAD + k];
        float a3 = sA[(mt * 4 + 3) * APAD + k];
        float4 b = *(const float4*)&sW[k * 64 + nt * 4];
        acc[0][0] += a0 * b.x; acc[0][1] += a0 * b.y; acc[0][2] += a0 * b.z; acc[0][3] += a0 * b.w;
        acc[1][0] += a1 * b.x; acc[1][1] += a1 * b.y; acc[1][2] += a1 * b.z; acc[1][3] += a1 * b.w;
        acc[2][0] += a2 * b.x; acc[2][1] += a2 * b.y; acc[2][2] += a2 * b.z; acc[2][3] += a2 * b.w;
        acc[3][0] += a3 * b.x; acc[3][1] += a3 * b.y; acc[3][2] += a3 * b.z; acc[3][3] += a3 * b.w;
    }

    // bias into regs before anyone overwrites sBias
    float bj0 = sBias[nt * 4 + 0];
    float bj1 = sBias[nt * 4 + 1];
    float bj2 = sBias[nt * 4 + 2];
    float bj3 = sBias[nt * 4 + 3];
    __syncthreads();   // done reading sA / sBias

    // mid = relu(acc + b1) -> back into sA; reload W2/b2
    #pragma unroll
    for (int i = 0; i < 4; i++) {
        float4 v;
        v.x = fmaxf(acc[i][0] + bj0, 0.f);
        v.y = fmaxf(acc[i][1] + bj1, 0.f);
        v.z = fmaxf(acc[i][2] + bj2, 0.f);
        v.w = fmaxf(acc[i][3] + bj3, 0.f);
        *(float4*)&sA[(mt * 4 + i) * APAD + nt * 4] = v;
    }
    for (int i = tid; i < 64 * 64; i += 256) sW[i] = Wb[i];
    if (tid < 64) sBias[tid] = bb[tid];
    __syncthreads();

    #pragma unroll
    for (int i = 0; i < 4; i++)
        #pragma unroll
        for (int j = 0; j < 4; j++) acc[i][j] = 0.f;

    // GEMM2: [64 x 64] @ [64 x 64]
    #pragma unroll 4
    for (int k = 0; k < 64; k++) {
        float a0 = sA[(mt * 4 + 0) * APAD + k];
        float a1 = sA[(mt * 4 + 1) * APAD + k];
        float a2 = sA[(mt * 4 + 2) * APAD + k];
        float a3 = sA[(mt * 4 + 3) * APAD + k];
        float4 b = *(const float4*)&sW[k * 64 + nt * 4];
        acc[0][0] += a0 * b.x; acc[0][1] += a0 * b.y; acc[0][2] += a0 * b.z; acc[0][3] += a0 * b.w;
        acc[1][0] += a1 * b.x; acc[1][1] += a1 * b.y; acc[1][2] += a1 * b.z; acc[1][3] += a1 * b.w;
        acc[2][0] += a2 * b.x; acc[2][1] += a2 * b.y; acc[2][2] += a2 * b.z; acc[2][3] += a2 * b.w;
        acc[3][0] += a3 * b.x; acc[3][1] += a3 * b.y; acc[3][2] += a3 * b.z; acc[3][3] += a3 * b.w;
    }

    float cj0 = sBias[nt * 4 + 0];
    float cj1 = sBias[nt * 4 + 1];
    float cj2 = sBias[nt * 4 + 2];
    float cj3 = sBias[nt * 4 + 3];

    float psum[4] = {0.f, 0.f, 0.f, 0.f};
    float psq[4]  = {0.f, 0.f, 0.f, 0.f};

    #pragma unroll
    for (int i = 0; i < 4; i++) {
        float4 v;
        v.x = fmaxf(acc[i][0] + cj0, 0.f);
        v.y = fmaxf(acc[i][1] + cj1, 0.f);
        v.z = fmaxf(acc[i][2] + cj2, 0.f);
        v.w = fmaxf(acc[i][3] + cj3, 0.f);
        size_t row = (size_t)(nb + mt * 4 + i) * 64 + (size_t)nt * 4;
        *(float4*)&g_h[row] = v;
        if (WRITE_AGG) *(float4*)&g_agg[row] = v;
        psum[0] += v.x; psq[0] += v.x * v.x;
        psum[1] += v.y; psq[1] += v.y * v.y;
        psum[2] += v.z; psq[2] += v.z * v.z;
        psum[3] += v.w; psq[3] += v.w * v.w;
    }

    // reduce lane l <-> l^16 (same nt, adjacent mt), then shared atomics
    #pragma unroll
    for (int j = 0; j < 4; j++) {
        psum[j] += __shfl_xor_sync(0xffffffffu, psum[j], 16);
        psq[j]  += __shfl_xor_sync(0xffffffffu, psq[j], 16);
    }
    if ((tid & 16) == 0) {
        #pragma unroll
        for (int j = 0; j < 4; j++) {
            atomicAdd(&sStat[nt * 4 + j], psum[j]);
            atomicAdd(&sStat[64 + nt * 4 + j], psq[j]);
        }
    }
    __syncthreads();
    if (tid < 128) atomicAdd(&g_stat[stat_out_off + tid], sStat[tid]);
}

// -------- final: BN3 + per-graph sum-pool + fc --------
__global__ __launch_bounds__(64) void k_final(
    const float* __restrict__ g3, const float* __restrict__ be3,
    const float* __restrict__ Wfc, const float* __restrict__ bfc,
    float* __restrict__ out)
{
    int g = blockIdx.x;
    int c = threadIdx.x;  // 0..63

    float sum = g_stat[4 * 64 + c];
    float sq  = g_stat[5 * 64 + c];
    float mean = sum / FN;
    float var  = sq / FN - mean * mean;
    float inv  = rsqrtf(var + BN_EPS);
    float s    = g3[c] * inv;
    float t    = be3[c] - mean * s;

    const float* base = g_h + (size_t)g * NPG * 64;
    float acc = 0.f;
    #pragma unroll 2
    for (int i = 0; i < NPG; i++) acc += base[(size_t)i * 64 + c];
    float pool = s * acc + (float)NPG * t;

    __shared__ float red[3][64];
    red[0][c] = pool * Wfc[c * 3 + 0];
    red[1][c] = pool * Wfc[c * 3 + 1];
    red[2][c] = pool * Wfc[c * 3 + 2];
    __syncthreads();
    if (c < 3) {
        float a = 0.f;
        #pragma unroll
        for (int i = 0; i < 64; i++) a += red[c][i];
        out[(size_t)g * 3 + c] = a + bfc[c];
    }
}

// -------- launch --------
extern "C" void kernel_launch(void* const* d_in, const int* in_sizes, int n_in,
                              void* d_out, int out_size) {
    (void)in_sizes; (void)n_in; (void)out_size;
    const float* x   = (const float*)d_in[0];
    const int*   src = (const int*)d_in[1];
    const int*   dst = (const int*)d_in[2];
    // d_in[3] = num_graphs (compile-time constant here)
    const float* W1a = (const float*)d_in[4];
    const float* b1a = (const float*)d_in[5];
    const float* W1b = (const float*)d_in[6];
    const float* b1b = (const float*)d_in[7];
    const float* g1  = (const float*)d_in[8];
    const float* be1 = (const float*)d_in[9];
    const float* W2a = (const float*)d_in[10];
    const float* b2a = (const float*)d_in[11];
    const float* W2b = (const float*)d_in[12];
    const float* b2b = (const float*)d_in[13];
    const float* g2  = (const float*)d_in[14];
    const float* be2 = (const float*)d_in[15];
    const float* W3a = (const float*)d_in[16];
    const float* b3a = (const float*)d_in[17];
    const float* W3b = (const float*)d_in[18];
    const float* b3b = (const float*)d_in[19];
    const float* g3  = (const float*)d_in[20];
    const float* be3 = (const float*)d_in[21];
    const float* Wfc = (const float*)d_in[22];
    const float* bfc = (const float*)d_in[23];
    float* out = (float*)d_out;

    const int TPB = 256;
    k_zero<<<(NNODES + TPB - 1) / TPB, TPB>>>();
    k_deg<<<(NEDGES + TPB - 1) / TPB, TPB>>>(dst);
    k_initagg1<<<(NNODES + TPB - 1) / TPB, TPB>>>(x);
    k_edge1<<<(NEDGES + TPB - 1) / TPB, TPB>>>(x, src, dst);

    // layer 1: input 4ch, no BN fold; write agg for layer 2
    k_mlp<4, false, true><<<NNODES / 64, TPB>>>(W1a, b1a, W1b, b1b, nullptr, nullptr, 0, 0);

    k_edge64<<<(NEDGES * 16 + TPB - 1) / TPB, TPB>>>(src, dst);
    // layer 2: fold BN1 into input
    k_mlp<64, true, true><<<NNODES / 64, TPB>>>(W2a, b2a, W2b, b2b, g1, be1, 0, 128);

    k_edge64<<<(NEDGES * 16 + TPB - 1) / TPB, TPB>>>(src, dst);
    // layer 3: fold BN2 into input; no agg write
    k_mlp<64, true, false><<<NNODES / 64, TPB>>>(W3a, b3a, W3b, b3b, g2, be2, 128, 256);

    // BN3 + pool + classifier
    k_final<<<NGRAPHS, 64>>>(g3, be3, Wfc, bfc, out);
}